// round 5
// baseline (speedup 1.0000x reference)
#include <cuda_runtime.h>
#include <cuda_fp16.h>
#include <stdint.h>

#define B_ 16
#define C_ 4
#define L_ 4096
#define K_ 256
#define S_ 128
#define W_ (L_ - S_ + 1)   // 3969
#define EPS_ 1e-8f

#define WT 256             // w per block (MMA M)
#define KT 128             // k per block (MMA N)

// Shapelets normalized -> fp16, PRE-SWIZZLED per-(ktile,channel) 32KB tile
// (256B rows, XOR-swizzled 16B chunks) so staging is a linear cp.async copy.
__device__ __align__(256) half g_shpB[C_ * K_ * S_];   // [2 ktiles][4 c][16K half]
__device__ float g_inv[B_ * C_ * W_];

// ---------------------------------------------------------------------------
// Normalize shapelets -> half into swizzled tile image; also zero the output.
__global__ void k_norm_shp(const float* __restrict__ shp, float* __restrict__ out) {
    int c = blockIdx.x >> 8;
    int k = blockIdx.x & 255;
    int s = threadIdx.x;
    int gi = blockIdx.x * 128 + threadIdx.x;      // fused output zeroing
    if (gi < B_ * K_) out[gi] = 0.f;

    float v = shp[(c * K_ + k) * S_ + s];
    float sq = v * v;
#pragma unroll
    for (int o = 16; o > 0; o >>= 1) sq += __shfl_xor_sync(0xffffffffu, sq, o);
    __shared__ float wsum[4];
    if ((threadIdx.x & 31) == 0) wsum[threadIdx.x >> 5] = sq;
    __syncthreads();
    float tot = wsum[0] + wsum[1] + wsum[2] + wsum[3];
    float inv = 1.f / fmaxf(sqrtf(tot), EPS_);
    int tile = (k >> 7) * C_ + c;
    int row = k & 127;
    uint32_t off = (uint32_t)row * 256u + ((((uint32_t)(s >> 3)) ^ (row & 7)) << 4)
                 + (uint32_t)(s & 7) * 2u;
    *(half*)((char*)g_shpB + (size_t)tile * 32768 + off) = __float2half(v * inv);
}

// Sliding-window inverse norms.
__global__ void k_inv_norm(const float* __restrict__ x) {
    __shared__ float xs[256 + S_ - 1];
    int bc = blockIdx.x;
    int w0 = blockIdx.y * 256;
    int tid = threadIdx.x;
    for (int i = tid; i < 256 + S_ - 1; i += 256) {
        int g = w0 + i;
        xs[i] = (g < L_) ? x[bc * L_ + g] : 0.f;
    }
    __syncthreads();
    int w = w0 + tid;
    if (w < W_) {
        float sum = 0.f;
#pragma unroll 8
        for (int s = 0; s < S_; s++) { float t = xs[tid + s]; sum += t * t; }
        g_inv[bc * W_ + w] = 1.f / fmaxf(sqrtf(sum), EPS_);
    }
}

// ---------------------------------------------------------------------------
__device__ __forceinline__ void ldsm4(uint32_t (&r)[4], uint32_t addr) {
    asm volatile("ldmatrix.sync.aligned.m8n8.x4.shared.b16 {%0,%1,%2,%3}, [%4];"
                 : "=r"(r[0]), "=r"(r[1]), "=r"(r[2]), "=r"(r[3]) : "r"(addr));
}
__device__ __forceinline__ void mma16816(float (&d)[4], const uint32_t (&a)[4],
                                         uint32_t b0, uint32_t b1) {
    asm volatile("mma.sync.aligned.m16n8k16.row.col.f32.f16.f16.f32 "
                 "{%0,%1,%2,%3}, {%4,%5,%6,%7}, {%8,%9}, {%0,%1,%2,%3};"
                 : "+f"(d[0]), "+f"(d[1]), "+f"(d[2]), "+f"(d[3])
                 : "r"(a[0]), "r"(a[1]), "r"(a[2]), "r"(a[3]), "r"(b0), "r"(b1));
}
__device__ __forceinline__ void cp16(uint32_t dst, const void* src) {
    asm volatile("cp.async.cg.shared.global [%0], [%1], 16;"
                 :: "r"(dst), "l"(src) : "memory");
}

// dynamic smem layout (bytes)
#define SM_A   0                   // 65536 : A tile 256w x 128s (normalized windows)
#define SM_B   65536               // 2 x 32768 : B tiles (double buffer)
#define SM_XS  131072              // 1536 : raw x strip (383 floats)
#define SM_IV  132608              // 1024 : inv norms (256 floats)
#define SM_MAX 133632              // 512  : per-k running max
#define SMEM_TOT 134144

// ---------------------------------------------------------------------------
// Main: 8 warps as 4(w) x 2(k); warp tile 64w x 64k; fp16 MMA, f32 accumulate
// across channels; inv_norm folded into A; relu/max fused epilogue.
// ---------------------------------------------------------------------------
__global__ void __launch_bounds__(256, 1) k_main(const float* __restrict__ x,
                                                 float* __restrict__ out) {
    extern __shared__ char dsm[];
    half*  As   = (half*)(dsm + SM_A);
    float* xs   = (float*)(dsm + SM_XS);
    float* iv   = (float*)(dsm + SM_IV);
    float* smax = (float*)(dsm + SM_MAX);
    const uint32_t sA  = (uint32_t)__cvta_generic_to_shared(dsm + SM_A);
    const uint32_t sB0 = (uint32_t)__cvta_generic_to_shared(dsm + SM_B);

    const int tid  = threadIdx.x;
    const int lane = tid & 31, wid = tid >> 5;
    const int ww = wid >> 1;           // 0..3 : w direction (64 rows each)
    const int wk = wid & 1;            // 0..1 : k direction (64 cols each)
    const int w0 = blockIdx.x * WT, k0 = blockIdx.y * KT, b = blockIdx.z;

    if (tid < KT) smax[tid] = 0.f;

    // ldmatrix lane address components
    const int l15 = lane & 15;
    const int lhi = lane >> 4;
    const int aXor = l15 & 7;
    const uint32_t aRow = sA + (uint32_t)(ww * 64 + l15) * 256;
    const int brow = wk * 64 + ((lane >> 4) & 1) * 8 + (lane & 7);   // + p*16
    const int bhi  = (lane >> 3) & 1;

    float acc[4][8][4];
#pragma unroll
    for (int mi = 0; mi < 4; mi++)
#pragma unroll
        for (int ni = 0; ni < 8; ni++)
#pragma unroll
            for (int d = 0; d < 4; d++) acc[mi][ni][d] = 0.f;

    // ---- initial loads: x strip / inv for c=0, cp.async B0 -----------------
    {
        const float* xg = x + (b * C_) * L_;
        int g0 = w0 + tid;
        xs[tid] = (g0 < L_) ? xg[g0] : 0.f;
        if (tid < WT + S_ - 1 - 256) {
            int g1 = w0 + 256 + tid;
            xs[256 + tid] = (g1 < L_) ? xg[g1] : 0.f;
        }
        int w = w0 + tid;
        iv[tid] = (w < W_) ? g_inv[(b * C_) * W_ + w] : 0.f;

        const char* src = (const char*)g_shpB + (size_t)(blockIdx.y * C_) * 32768;
#pragma unroll
        for (int j = 0; j < 8; j++) {
            int idx = tid + 256 * j;
            cp16(sB0 + idx * 16, src + idx * 16);
        }
        asm volatile("cp.async.commit_group;" ::: "memory");
    }
    __syncthreads();

    for (int c = 0; c < C_; c++) {
        // ---- build A[w][s] = xs[w+s] * iv[w], 256 rows ---------------------
#pragma unroll
        for (int r2 = 0; r2 < 2; r2++) {
            int w = (tid & 127) + r2 * 128;
            int hf = tid >> 7;                       // half-row: s 0..63 / 64..127
            float s = iv[w];
            const float* xp = xs + w + hf * 64;
            char* rowp = (char*)As + w * 256;
            int swz = w & 7;
#pragma unroll
            for (int jj = 0; jj < 8; jj++) {
                int ci = hf * 8 + jj;
                const float* p = xp + jj * 8;
                half2 h0 = __floats2half2_rn(s * p[0], s * p[1]);
                half2 h1 = __floats2half2_rn(s * p[2], s * p[3]);
                half2 h2 = __floats2half2_rn(s * p[4], s * p[5]);
                half2 h3 = __floats2half2_rn(s * p[6], s * p[7]);
                uint4 u;
                u.x = *(uint32_t*)&h0; u.y = *(uint32_t*)&h1;
                u.z = *(uint32_t*)&h2; u.w = *(uint32_t*)&h3;
                *(uint4*)(rowp + ((ci ^ swz) << 4)) = u;
            }
        }
        // ---- prefetch next channel strip (regs) + cp.async next B ----------
        float px0 = 0.f, px1 = 0.f, piv = 0.f;
        if (c + 1 < C_) {
            const float* xg = x + (b * C_ + c + 1) * L_;
            int g0 = w0 + tid;
            px0 = (g0 < L_) ? xg[g0] : 0.f;
            if (tid < WT + S_ - 1 - 256) {
                int g1 = w0 + 256 + tid;
                px1 = (g1 < L_) ? xg[g1] : 0.f;
            }
            int w = w0 + tid;
            piv = (w < W_) ? g_inv[(b * C_ + c + 1) * W_ + w] : 0.f;

            const char* src = (const char*)g_shpB
                            + (size_t)(blockIdx.y * C_ + c + 1) * 32768;
            uint32_t dst = sB0 + ((c + 1) & 1) * 32768;
#pragma unroll
            for (int j = 0; j < 8; j++) {
                int idx = tid + 256 * j;
                cp16(dst + idx * 16, src + idx * 16);
            }
            asm volatile("cp.async.commit_group;" ::: "memory");
            asm volatile("cp.async.wait_group 1;" ::: "memory");
        } else {
            asm volatile("cp.async.wait_group 0;" ::: "memory");
        }
        __syncthreads();   // A built, B_c landed

        // ---- MMA mainloop: 8 s-steps of 16 ---------------------------------
        const uint32_t sB = sB0 + (c & 1) * 32768;
#pragma unroll
        for (int st = 0; st < 8; st++) {
            uint32_t a[4][4];
#pragma unroll
            for (int mi = 0; mi < 4; mi++)
                ldsm4(a[mi], aRow + (uint32_t)mi * 4096
                             + (uint32_t)(((2 * st + lhi) ^ aXor) << 4));
            uint32_t bb[4][4];
#pragma unroll
            for (int p = 0; p < 4; p++) {
                int row = brow + p * 16;
                uint32_t ad = sB + row * 256 + (((2 * st + bhi) ^ (row & 7)) << 4);
                ldsm4(bb[p], ad);
            }
#pragma unroll
            for (int mi = 0; mi < 4; mi++)
#pragma unroll
                for (int p = 0; p < 4; p++) {
                    mma16816(acc[mi][2 * p + 0], a[mi], bb[p][0], bb[p][1]);
                    mma16816(acc[mi][2 * p + 1], a[mi], bb[p][2], bb[p][3]);
                }
        }
        __syncthreads();   // A/xs/iv free for next channel

        if (c + 1 < C_) {
            xs[tid] = px0;
            if (tid < WT + S_ - 1 - 256) xs[256 + tid] = px1;
            iv[tid] = piv;
            __syncthreads();
        }
    }

    // ---- epilogue: relu + max over w, reduce to out[b][k] -------------------
#pragma unroll
    for (int ni = 0; ni < 8; ni++) {
#pragma unroll
        for (int cc = 0; cc < 2; cc++) {
            float m0 = fmaxf(fmaxf(acc[0][ni][cc], acc[0][ni][cc + 2]),
                             fmaxf(acc[1][ni][cc], acc[1][ni][cc + 2]));
            float m1 = fmaxf(fmaxf(acc[2][ni][cc], acc[2][ni][cc + 2]),
                             fmaxf(acc[3][ni][cc], acc[3][ni][cc + 2]));
            float m = fmaxf(m0, m1);
            m = fmaxf(m * 0.25f, 0.f);
            m = fmaxf(m, __shfl_xor_sync(0xffffffffu, m, 4));
            m = fmaxf(m, __shfl_xor_sync(0xffffffffu, m, 8));
            m = fmaxf(m, __shfl_xor_sync(0xffffffffu, m, 16));
            if (lane < 4)
                atomicMax((int*)&smax[wk * 64 + ni * 8 + 2 * lane + cc],
                          __float_as_int(m));
        }
    }
    __syncthreads();
    if (tid < KT)
        atomicMax((int*)&out[b * K_ + k0 + tid], __float_as_int(smax[tid]));
}

// ---------------------------------------------------------------------------
extern "C" void kernel_launch(void* const* d_in, const int* in_sizes, int n_in,
                              void* d_out, int out_size) {
    const float* x   = (const float*)d_in[0];   // (16,4,4096)
    const float* shp = (const float*)d_in[1];   // (4,256,128)
    float* out = (float*)d_out;                 // (16,1,256)

    static int attr_done = 0;
    if (!attr_done) {
        cudaFuncSetAttribute(k_main, cudaFuncAttributeMaxDynamicSharedMemorySize,
                             SMEM_TOT);
        attr_done = 1;
    }

    k_norm_shp<<<C_ * K_, S_>>>(shp, out);
    k_inv_norm<<<dim3(B_ * C_, (W_ + 255) / 256), 256>>>(x);
    k_main<<<dim3((W_ + WT - 1) / WT, K_ / KT, B_), 256, SMEM_TOT>>>(x, out);
}

// round 6
// speedup vs baseline: 1.0907x; 1.0907x over previous
#include <cuda_runtime.h>
#include <cuda_fp16.h>
#include <stdint.h>

#define B_ 16
#define C_ 4
#define L_ 4096
#define K_ 256
#define S_ 128
#define W_ (L_ - S_ + 1)   // 3969
#define EPS_ 1e-8f

#define WT 128             // w per block (MMA M)
#define KT 128             // k per block (MMA N)

// Shapelets normalized -> fp16, PRE-SWIZZLED per-(ktile,channel) 32KB tile
// (256B rows, XOR-swizzled 16B chunks) so staging is a linear cp.async copy.
__device__ __align__(256) half g_shpB[C_ * K_ * S_];   // [2 ktiles][4 c][16K half]
__device__ float g_inv[B_ * C_ * W_];

// ---------------------------------------------------------------------------
// Normalize shapelets -> half into swizzled tile image; also zero the output.
__global__ void k_norm_shp(const float* __restrict__ shp, float* __restrict__ out) {
    int c = blockIdx.x >> 8;
    int k = blockIdx.x & 255;
    int s = threadIdx.x;
    int gi = blockIdx.x * 128 + threadIdx.x;      // fused output zeroing
    if (gi < B_ * K_) out[gi] = 0.f;

    float v = shp[(c * K_ + k) * S_ + s];
    float sq = v * v;
#pragma unroll
    for (int o = 16; o > 0; o >>= 1) sq += __shfl_xor_sync(0xffffffffu, sq, o);
    __shared__ float wsum[4];
    if ((threadIdx.x & 31) == 0) wsum[threadIdx.x >> 5] = sq;
    __syncthreads();
    float tot = wsum[0] + wsum[1] + wsum[2] + wsum[3];
    float inv = 1.f / fmaxf(sqrtf(tot), EPS_);
    int tile = (k >> 7) * C_ + c;
    int row = k & 127;
    uint32_t off = (uint32_t)row * 256u + ((((uint32_t)(s >> 3)) ^ (row & 7)) << 4)
                 + (uint32_t)(s & 7) * 2u;
    *(half*)((char*)g_shpB + (size_t)tile * 32768 + off) = __float2half(v * inv);
}

// Sliding-window inverse norms.
__global__ void k_inv_norm(const float* __restrict__ x) {
    __shared__ float xs[256 + S_ - 1];
    int bc = blockIdx.x;
    int w0 = blockIdx.y * 256;
    int tid = threadIdx.x;
    for (int i = tid; i < 256 + S_ - 1; i += 256) {
        int g = w0 + i;
        xs[i] = (g < L_) ? x[bc * L_ + g] : 0.f;
    }
    __syncthreads();
    int w = w0 + tid;
    if (w < W_) {
        float sum = 0.f;
#pragma unroll 8
        for (int s = 0; s < S_; s++) { float t = xs[tid + s]; sum += t * t; }
        g_inv[bc * W_ + w] = 1.f / fmaxf(sqrtf(sum), EPS_);
    }
}

// ---------------------------------------------------------------------------
__device__ __forceinline__ void ldsm4(uint32_t (&r)[4], uint32_t addr) {
    asm volatile("ldmatrix.sync.aligned.m8n8.x4.shared.b16 {%0,%1,%2,%3}, [%4];"
                 : "=r"(r[0]), "=r"(r[1]), "=r"(r[2]), "=r"(r[3]) : "r"(addr));
}
__device__ __forceinline__ void mma16816(float (&d)[4], const uint32_t (&a)[4],
                                         uint32_t b0, uint32_t b1) {
    asm volatile("mma.sync.aligned.m16n8k16.row.col.f32.f16.f16.f32 "
                 "{%0,%1,%2,%3}, {%4,%5,%6,%7}, {%8,%9}, {%0,%1,%2,%3};"
                 : "+f"(d[0]), "+f"(d[1]), "+f"(d[2]), "+f"(d[3])
                 : "r"(a[0]), "r"(a[1]), "r"(a[2]), "r"(a[3]), "r"(b0), "r"(b1));
}
__device__ __forceinline__ void cp16(uint32_t dst, const void* src) {
    asm volatile("cp.async.cg.shared.global [%0], [%1], 16;"
                 :: "r"(dst), "l"(src) : "memory");
}

// dynamic smem layout (bytes)
#define SM_A   0                   // 32768 : A tile (normalized windows)
#define SM_B   32768               // 2 x 32768 : B tiles (double buffer)
#define SM_XS  (32768 * 3)         // 2 x 1024 : raw x strips (255 floats, dbl buf)
#define SM_IV  (SM_XS + 2048)      // 2 x 512  : inv norms (128 floats, dbl buf)
#define SM_MAX (SM_IV + 1024)      // 512  : per-k running max
#define SMEM_TOT (SM_MAX + 512)

// ---------------------------------------------------------------------------
// Main: 128 threads = 4 warps as 2(w) x 2(k); warp tile 64w x 64k.
// fp16 MMA, f32 accumulate across channels; inv_norm folded into A;
// relu/max fused epilogue. 2 CTAs/SM for staging/MMA overlap.
// ---------------------------------------------------------------------------
__global__ void __launch_bounds__(128, 2) k_main(const float* __restrict__ x,
                                                 float* __restrict__ out) {
    extern __shared__ char dsm[];
    half*  As   = (half*)(dsm + SM_A);
    float* smax = (float*)(dsm + SM_MAX);
    const uint32_t sA  = (uint32_t)__cvta_generic_to_shared(dsm + SM_A);
    const uint32_t sB0 = (uint32_t)__cvta_generic_to_shared(dsm + SM_B);

    const int tid  = threadIdx.x;
    const int lane = tid & 31, wid = tid >> 5;
    const int ww = wid & 1;            // w direction (64 rows each)
    const int wk = wid >> 1;           // k direction (64 cols each)
    const int w0 = blockIdx.x * WT, k0 = blockIdx.y * KT, b = blockIdx.z;

    smax[tid] = 0.f;

    // ldmatrix lane address components
    const int l15 = lane & 15;
    const int lhi = lane >> 4;
    const int aXor = l15 & 7;
    const uint32_t aRow = sA + (uint32_t)(ww * 64 + l15) * 256;
    const int brow = wk * 64 + ((lane >> 4) & 1) * 8 + (lane & 7);   // + p*16
    const int bhi  = (lane >> 3) & 1;

    float acc[4][8][4];
#pragma unroll
    for (int mi = 0; mi < 4; mi++)
#pragma unroll
        for (int ni = 0; ni < 8; ni++)
#pragma unroll
            for (int d = 0; d < 4; d++) acc[mi][ni][d] = 0.f;

    // ---- initial loads: x strip / inv for c=0 into buffer 0, cp.async B0 ---
    {
        float* xs0 = (float*)(dsm + SM_XS);
        float* iv0 = (float*)(dsm + SM_IV);
        const float* xg = x + (b * C_) * L_;
        int g0 = w0 + tid;
        xs0[tid] = (g0 < L_) ? xg[g0] : 0.f;
        if (tid < WT + S_ - 1 - 128) {
            int g1 = w0 + 128 + tid;
            xs0[128 + tid] = (g1 < L_) ? xg[g1] : 0.f;
        }
        int w = w0 + tid;
        iv0[tid] = (w < W_) ? g_inv[(b * C_) * W_ + w] : 0.f;

        const char* src = (const char*)g_shpB + (size_t)(blockIdx.y * C_) * 32768;
#pragma unroll
        for (int j = 0; j < 16; j++) {
            int idx = tid + 128 * j;
            cp16(sB0 + idx * 16, src + idx * 16);
        }
        asm volatile("cp.async.commit_group;" ::: "memory");
    }
    __syncthreads();

    for (int c = 0; c < C_; c++) {
        const int cb = c & 1;
        float* xs = (float*)(dsm + SM_XS + cb * 1024);
        float* iv = (float*)(dsm + SM_IV + cb * 512);

        // ---- build A[w][s] = xs[w+s] * iv[w]; thread = one w-row -----------
        {
            int w = tid;
            float s = iv[w];
            const float* xp = xs + w;
            char* rowp = (char*)As + w * 256;
            int swz = w & 7;
#pragma unroll
            for (int jj = 0; jj < 16; jj++) {
                const float* p = xp + jj * 8;
                half2 h0 = __floats2half2_rn(s * p[0], s * p[1]);
                half2 h1 = __floats2half2_rn(s * p[2], s * p[3]);
                half2 h2 = __floats2half2_rn(s * p[4], s * p[5]);
                half2 h3 = __floats2half2_rn(s * p[6], s * p[7]);
                uint4 u;
                u.x = *(uint32_t*)&h0; u.y = *(uint32_t*)&h1;
                u.z = *(uint32_t*)&h2; u.w = *(uint32_t*)&h3;
                *(uint4*)(rowp + ((jj ^ swz) << 4)) = u;
            }
        }

        // ---- prefetch channel c+1 into the other xs/iv buffer + next B -----
        if (c + 1 < C_) {
            float* xsn = (float*)(dsm + SM_XS + (cb ^ 1) * 1024);
            float* ivn = (float*)(dsm + SM_IV + (cb ^ 1) * 512);
            const float* xg = x + (b * C_ + c + 1) * L_;
            int g0 = w0 + tid;
            xsn[tid] = (g0 < L_) ? xg[g0] : 0.f;
            if (tid < WT + S_ - 1 - 128) {
                int g1 = w0 + 128 + tid;
                xsn[128 + tid] = (g1 < L_) ? xg[g1] : 0.f;
            }
            int w = w0 + tid;
            ivn[tid] = (w < W_) ? g_inv[(b * C_ + c + 1) * W_ + w] : 0.f;

            const char* src = (const char*)g_shpB
                            + (size_t)(blockIdx.y * C_ + c + 1) * 32768;
            uint32_t dst = sB0 + ((c + 1) & 1) * 32768;
#pragma unroll
            for (int j = 0; j < 16; j++) {
                int idx = tid + 128 * j;
                cp16(dst + idx * 16, src + idx * 16);
            }
            asm volatile("cp.async.commit_group;" ::: "memory");
            asm volatile("cp.async.wait_group 1;" ::: "memory");
        } else {
            asm volatile("cp.async.wait_group 0;" ::: "memory");
        }
        __syncthreads();   // A built, B_c landed

        // ---- MMA mainloop: 8 s-steps of 16; warp tile 64w x 64k ------------
        const uint32_t sB = sB0 + cb * 32768;
#pragma unroll
        for (int st = 0; st < 8; st++) {
            uint32_t a[4][4];
#pragma unroll
            for (int mi = 0; mi < 4; mi++)
                ldsm4(a[mi], aRow + (uint32_t)mi * 4096
                             + (uint32_t)(((2 * st + lhi) ^ aXor) << 4));
            uint32_t bb[4][4];
#pragma unroll
            for (int p = 0; p < 4; p++) {
                int row = brow + p * 16;
                uint32_t ad = sB + row * 256 + (((2 * st + bhi) ^ (row & 7)) << 4);
                ldsm4(bb[p], ad);
            }
#pragma unroll
            for (int mi = 0; mi < 4; mi++)
#pragma unroll
                for (int p = 0; p < 4; p++) {
                    mma16816(acc[mi][2 * p + 0], a[mi], bb[p][0], bb[p][1]);
                    mma16816(acc[mi][2 * p + 1], a[mi], bb[p][2], bb[p][3]);
                }
        }
        __syncthreads();   // A + xs/iv(c) free for next channel
    }

    // ---- epilogue: relu + max over w, reduce to out[b][k] -------------------
#pragma unroll
    for (int ni = 0; ni < 8; ni++) {
#pragma unroll
        for (int cc = 0; cc < 2; cc++) {
            float m0 = fmaxf(fmaxf(acc[0][ni][cc], acc[0][ni][cc + 2]),
                             fmaxf(acc[1][ni][cc], acc[1][ni][cc + 2]));
            float m1 = fmaxf(fmaxf(acc[2][ni][cc], acc[2][ni][cc + 2]),
                             fmaxf(acc[3][ni][cc], acc[3][ni][cc + 2]));
            float m = fmaxf(m0, m1);
            m = fmaxf(m * 0.25f, 0.f);
            m = fmaxf(m, __shfl_xor_sync(0xffffffffu, m, 4));
            m = fmaxf(m, __shfl_xor_sync(0xffffffffu, m, 8));
            m = fmaxf(m, __shfl_xor_sync(0xffffffffu, m, 16));
            if (lane < 4)
                atomicMax((int*)&smax[wk * 64 + ni * 8 + 2 * lane + cc],
                          __float_as_int(m));
        }
    }
    __syncthreads();
    atomicMax((int*)&out[b * K_ + k0 + tid], __float_as_int(smax[tid]));
}

// ---------------------------------------------------------------------------
extern "C" void kernel_launch(void* const* d_in, const int* in_sizes, int n_in,
                              void* d_out, int out_size) {
    const float* x   = (const float*)d_in[0];   // (16,4,4096)
    const float* shp = (const float*)d_in[1];   // (4,256,128)
    float* out = (float*)d_out;                 // (16,1,256)

    static int attr_done = 0;
    if (!attr_done) {
        cudaFuncSetAttribute(k_main, cudaFuncAttributeMaxDynamicSharedMemorySize,
                             SMEM_TOT);
        attr_done = 1;
    }

    k_norm_shp<<<C_ * K_, S_>>>(shp, out);
    k_inv_norm<<<dim3(B_ * C_, (W_ + 255) / 256), 256>>>(x);
    k_main<<<dim3((W_ + WT - 1) / WT, K_ / KT, B_), 128, SMEM_TOT>>>(x, out);
}

// round 7
// speedup vs baseline: 1.3219x; 1.2120x over previous
#include <cuda_runtime.h>
#include <cuda_fp16.h>
#include <stdint.h>

#define B_ 16
#define C_ 4
#define L_ 4096
#define K_ 256
#define S_ 128
#define W_ (L_ - S_ + 1)   // 3969
#define EPS_ 1e-8f

#define WT 128             // w per block (MMA M)
#define KT 128             // k per block (MMA N)

// Shapelets normalized -> fp16, PRE-SWIZZLED per-(ktile,channel) 32KB tile
// (256B rows, XOR-swizzled 16B chunks) so staging is a linear cp.async copy.
__device__ __align__(256) half g_shpB[C_ * K_ * S_];   // [2 ktiles][4 c][16K half]
__device__ __half g_invh[B_ * C_ * W_];                // 1/||window||, fp16

// ---------------------------------------------------------------------------
// Merged prep kernel:
//  blocks [0,1024): sliding-window inverse norms (+ zero out on blocks [0,16))
//  blocks [1024,1536): shapelet normalize -> swizzled fp16 image (2 (c,k)/blk)
// ---------------------------------------------------------------------------
__global__ void k_prep(const float* __restrict__ x, const float* __restrict__ shp,
                       float* __restrict__ out) {
    int tid = threadIdx.x;
    if (blockIdx.x < 1024) {
        __shared__ float xs[256 + S_ - 1];
        int bc = blockIdx.x >> 4;
        int w0 = (blockIdx.x & 15) * 256;
        if (blockIdx.x < 16) out[blockIdx.x * 256 + tid] = 0.f;
        for (int i = tid; i < 256 + S_ - 1; i += 256) {
            int g = w0 + i;
            xs[i] = (g < L_) ? x[bc * L_ + g] : 0.f;
        }
        __syncthreads();
        int w = w0 + tid;
        if (w < W_) {
            float sum = 0.f;
#pragma unroll 8
            for (int s = 0; s < S_; s++) { float t = xs[tid + s]; sum += t * t; }
            g_invh[bc * W_ + w] = __float2half(1.f / fmaxf(sqrtf(sum), EPS_));
        }
    } else {
        __shared__ float wsum[8];
        int idx = blockIdx.x - 1024;              // 0..511
        int p = idx * 2 + (tid >> 7);             // (c,k) pair id, 0..1023
        int c = p >> 8, k = p & 255;
        int s = tid & 127;
        float v = shp[(c * K_ + k) * S_ + s];
        float sq = v * v;
#pragma unroll
        for (int o = 16; o > 0; o >>= 1) sq += __shfl_xor_sync(0xffffffffu, sq, o);
        if ((tid & 31) == 0) wsum[tid >> 5] = sq;
        __syncthreads();
        int g4 = (tid >> 7) * 4;
        float tot = wsum[g4] + wsum[g4 + 1] + wsum[g4 + 2] + wsum[g4 + 3];
        float inv = 1.f / fmaxf(sqrtf(tot), EPS_);
        int tile = (k >> 7) * C_ + c;
        int row = k & 127;
        uint32_t off = (uint32_t)row * 256u
                     + ((((uint32_t)(s >> 3)) ^ (row & 7)) << 4)
                     + (uint32_t)(s & 7) * 2u;
        *(half*)((char*)g_shpB + (size_t)tile * 32768 + off) = __float2half(v * inv);
    }
}

// ---------------------------------------------------------------------------
__device__ __forceinline__ void ldsm4(uint32_t (&r)[4], uint32_t addr) {
    asm volatile("ldmatrix.sync.aligned.m8n8.x4.shared.b16 {%0,%1,%2,%3}, [%4];"
                 : "=r"(r[0]), "=r"(r[1]), "=r"(r[2]), "=r"(r[3]) : "r"(addr));
}
__device__ __forceinline__ void mma16816(float (&d)[4], const uint32_t (&a)[4],
                                         uint32_t b0, uint32_t b1) {
    asm volatile("mma.sync.aligned.m16n8k16.row.col.f32.f16.f16.f32 "
                 "{%0,%1,%2,%3}, {%4,%5,%6,%7}, {%8,%9}, {%0,%1,%2,%3};"
                 : "+f"(d[0]), "+f"(d[1]), "+f"(d[2]), "+f"(d[3])
                 : "r"(a[0]), "r"(a[1]), "r"(a[2]), "r"(a[3]), "r"(b0), "r"(b1));
}
__device__ __forceinline__ void cp16(uint32_t dst, const void* src) {
    asm volatile("cp.async.cg.shared.global [%0], [%1], 16;"
                 :: "r"(dst), "l"(src) : "memory");
}

// dynamic smem layout (bytes)
#define SM_A     0                 // 32768 : A tile (normalized windows, fp16)
#define SM_B     32768             // 2 x 32768 : B tiles (double buffer)
#define SM_STRIP 98304             // 2 x 2048 : dual half2 strips + ivh (dbl buf)
//   per buffer: xe @ +0 (512B), xo @ +576 (512B, bank-shifted), ivh @ +1088 (256B)
#define SM_MAX   102400            // 512 : per-k running max
#define SMEM_TOT 102912

// ---------------------------------------------------------------------------
// Main: 256 thr = 8 warps as 4(w) x 2(k); warp tile 32w x 64k; fp16 MMA,
// f32 accumulate across channels; inv_norm folded into A (all-half build);
// relu/max fused epilogue. 2 CTAs/SM.
// ---------------------------------------------------------------------------
__global__ void __launch_bounds__(256, 2) k_main(const float* __restrict__ x,
                                                 float* __restrict__ out) {
    extern __shared__ char dsm[];
    half*  As   = (half*)(dsm + SM_A);
    float* smax = (float*)(dsm + SM_MAX);
    const uint32_t sA  = (uint32_t)__cvta_generic_to_shared(dsm + SM_A);
    const uint32_t sB0 = (uint32_t)__cvta_generic_to_shared(dsm + SM_B);

    const int tid  = threadIdx.x;
    const int lane = tid & 31, wid = tid >> 5;
    const int ww = wid & 3;            // w direction (32 rows each)
    const int wk = wid >> 2;           // k direction (64 cols each)
    const int w0 = blockIdx.x * WT, k0 = blockIdx.y * KT, b = blockIdx.z;

    if (tid < KT) smax[tid] = 0.f;

    // ldmatrix lane address components
    const int l15 = lane & 15;
    const int lhi = lane >> 4;
    const int aXor = l15 & 7;
    const uint32_t aRow = sA + (uint32_t)(ww * 32 + l15) * 256;
    const int brow = wk * 64 + ((lane >> 4) & 1) * 8 + (lane & 7);   // + p*16
    const int bhi  = (lane >> 3) & 1;

    float acc[2][8][4];
#pragma unroll
    for (int mi = 0; mi < 2; mi++)
#pragma unroll
        for (int ni = 0; ni < 8; ni++)
#pragma unroll
            for (int d = 0; d < 4; d++) acc[mi][ni][d] = 0.f;

    // ---- strip staging helper (channel ch -> buffer bf) --------------------
    // threads 0..127: dual even/odd half2 strips; threads 128..255: ivh.
#define STAGE_STRIP(ch, bf) do {                                               \
        char* sp = dsm + SM_STRIP + (bf) * 2048;                               \
        if (tid < 128) {                                                       \
            const float* xg = x + ((b * C_ + (ch)) * L_) + w0;                 \
            int i0 = 2 * tid;                                                  \
            float f0 = (w0 + i0     < L_) ? xg[i0]     : 0.f;                  \
            float f1 = (w0 + i0 + 1 < L_) ? xg[i0 + 1] : 0.f;                  \
            float f2 = (w0 + i0 + 2 < L_) ? xg[i0 + 2] : 0.f;                  \
            half2 e = __floats2half2_rn(f0, f1);                               \
            half2 o = __floats2half2_rn(f1, f2);                               \
            ((uint32_t*)(sp))[tid]        = *(uint32_t*)&e;                    \
            ((uint32_t*)(sp + 576))[tid]  = *(uint32_t*)&o;                    \
        } else {                                                               \
            int w = w0 + tid - 128;                                            \
            ((half*)(sp + 1088))[tid - 128] =                                  \
                (w < W_) ? g_invh[(b * C_ + (ch)) * W_ + w] : __float2half(0.f);\
        }                                                                      \
    } while (0)

    // ---- initial: strip c=0 -> buf0, cp.async B0 ----------------------------
    STAGE_STRIP(0, 0);
    {
        const char* src = (const char*)g_shpB + (size_t)(blockIdx.y * C_) * 32768;
#pragma unroll
        for (int j = 0; j < 8; j++) {
            int idx = tid + 256 * j;
            cp16(sB0 + idx * 16, src + idx * 16);
        }
        asm volatile("cp.async.commit_group;" ::: "memory");
    }
    __syncthreads();

    for (int c = 0; c < C_; c++) {
        const int cb = c & 1;
        char* sp = dsm + SM_STRIP + cb * 2048;

        // ---- build A[w][s] = xh[w+s] * ivh[w] (all-half, conflict-free) ----
        {
            int w = tid & 127, hf = tid >> 7;
            const uint32_t* xc = (w & 1) ? (const uint32_t*)(sp + 576)
                                         : (const uint32_t*)(sp);
            int base = (w >> 1) + hf * 32;
            half ivv = ((const half*)(sp + 1088))[w];
            half2 iv2 = __half2half2(ivv);
            char* rowp = (char*)As + w * 256;
            int swz = w & 7;
#pragma unroll
            for (int jj = 0; jj < 8; jj++) {
                uint32_t q0 = xc[base + jj * 4 + 0];
                uint32_t q1 = xc[base + jj * 4 + 1];
                uint32_t q2 = xc[base + jj * 4 + 2];
                uint32_t q3 = xc[base + jj * 4 + 3];
                half2 p0 = __hmul2(*(half2*)&q0, iv2);
                half2 p1 = __hmul2(*(half2*)&q1, iv2);
                half2 p2 = __hmul2(*(half2*)&q2, iv2);
                half2 p3 = __hmul2(*(half2*)&q3, iv2);
                uint4 u;
                u.x = *(uint32_t*)&p0; u.y = *(uint32_t*)&p1;
                u.z = *(uint32_t*)&p2; u.w = *(uint32_t*)&p3;
                *(uint4*)(rowp + (((hf * 8 + jj) ^ swz) << 4)) = u;
            }
        }

        // ---- stage strip c+1 (other buffer) + cp.async next B --------------
        if (c + 1 < C_) {
            STAGE_STRIP(c + 1, cb ^ 1);
            const char* src = (const char*)g_shpB
                            + (size_t)(blockIdx.y * C_ + c + 1) * 32768;
            uint32_t dst = sB0 + ((c + 1) & 1) * 32768;
#pragma unroll
            for (int j = 0; j < 8; j++) {
                int idx = tid + 256 * j;
                cp16(dst + idx * 16, src + idx * 16);
            }
            asm volatile("cp.async.commit_group;" ::: "memory");
            asm volatile("cp.async.wait_group 1;" ::: "memory");
        } else {
            asm volatile("cp.async.wait_group 0;" ::: "memory");
        }
        __syncthreads();   // A built, B_c landed

        // ---- MMA mainloop: 8 s-steps of 16 ---------------------------------
        const uint32_t sB = sB0 + cb * 32768;
#pragma unroll
        for (int st = 0; st < 8; st++) {
            uint32_t a[2][4];
#pragma unroll
            for (int mi = 0; mi < 2; mi++)
                ldsm4(a[mi], aRow + (uint32_t)mi * 4096
                             + (uint32_t)(((2 * st + lhi) ^ aXor) << 4));
            uint32_t bb[4][4];
#pragma unroll
            for (int p = 0; p < 4; p++) {
                int row = brow + p * 16;
                uint32_t ad = sB + row * 256 + (((2 * st + bhi) ^ (row & 7)) << 4);
                ldsm4(bb[p], ad);
            }
#pragma unroll
            for (int mi = 0; mi < 2; mi++)
#pragma unroll
                for (int p = 0; p < 4; p++) {
                    mma16816(acc[mi][2 * p + 0], a[mi], bb[p][0], bb[p][1]);
                    mma16816(acc[mi][2 * p + 1], a[mi], bb[p][2], bb[p][3]);
                }
        }
        __syncthreads();   // A free for next channel's build
    }

    // ---- epilogue: relu + max over w, reduce to out[b][k] -------------------
#pragma unroll
    for (int ni = 0; ni < 8; ni++) {
#pragma unroll
        for (int cc = 0; cc < 2; cc++) {
            float m = fmaxf(fmaxf(acc[0][ni][cc], acc[0][ni][cc + 2]),
                            fmaxf(acc[1][ni][cc], acc[1][ni][cc + 2]));
            m = fmaxf(m * 0.25f, 0.f);
            m = fmaxf(m, __shfl_xor_sync(0xffffffffu, m, 4));
            m = fmaxf(m, __shfl_xor_sync(0xffffffffu, m, 8));
            m = fmaxf(m, __shfl_xor_sync(0xffffffffu, m, 16));
            if (lane < 4)
                atomicMax((int*)&smax[wk * 64 + ni * 8 + 2 * lane + cc],
                          __float_as_int(m));
        }
    }
    __syncthreads();
    if (tid < KT)
        atomicMax((int*)&out[b * K_ + k0 + tid], __float_as_int(smax[tid]));
}

// ---------------------------------------------------------------------------
extern "C" void kernel_launch(void* const* d_in, const int* in_sizes, int n_in,
                              void* d_out, int out_size) {
    const float* x   = (const float*)d_in[0];   // (16,4,4096)
    const float* shp = (const float*)d_in[1];   // (4,256,128)
    float* out = (float*)d_out;                 // (16,1,256)

    static int attr_done = 0;
    if (!attr_done) {
        cudaFuncSetAttribute(k_main, cudaFuncAttributeMaxDynamicSharedMemorySize,
                             SMEM_TOT);
        attr_done = 1;
    }

    k_prep<<<1536, 256>>>(x, shp, out);
    k_main<<<dim3((W_ + WT - 1) / WT, K_ / KT, B_), 256, SMEM_TOT>>>(x, out);
}

// round 8
// speedup vs baseline: 1.4365x; 1.0867x over previous
#include <cuda_runtime.h>
#include <cuda_fp16.h>
#include <stdint.h>

#define B_ 16
#define C_ 4
#define L_ 4096
#define K_ 256
#define S_ 128
#define W_ (L_ - S_ + 1)   // 3969
#define EPS_ 1e-8f

#define WT 128             // w per block (MMA M)
#define KT 128             // k per block (MMA N)

// Shapelets normalized -> fp16, PRE-SWIZZLED per-(ktile,channel) 32KB tile
// (256B rows, XOR-swizzled 16B chunks) so staging is a linear cp.async copy.
__device__ __align__(256) half g_shpB[C_ * K_ * S_];   // [2 ktiles][4 c][16K half]
__device__ __half g_invh[B_ * C_ * W_];                // 1/||window||, fp16

// ---------------------------------------------------------------------------
// Merged prep kernel:
//  blocks [0,1024): sliding-window inverse norms (+ zero out on blocks [0,16))
//  blocks [1024,1536): shapelet normalize -> swizzled fp16 image (2 (c,k)/blk)
// ---------------------------------------------------------------------------
__global__ void k_prep(const float* __restrict__ x, const float* __restrict__ shp,
                       float* __restrict__ out) {
    int tid = threadIdx.x;
    if (blockIdx.x < 1024) {
        __shared__ float xs[256 + S_ - 1];
        int bc = blockIdx.x >> 4;
        int w0 = (blockIdx.x & 15) * 256;
        if (blockIdx.x < 16) out[blockIdx.x * 256 + tid] = 0.f;
        for (int i = tid; i < 256 + S_ - 1; i += 256) {
            int g = w0 + i;
            xs[i] = (g < L_) ? x[bc * L_ + g] : 0.f;
        }
        __syncthreads();
        int w = w0 + tid;
        if (w < W_) {
            float sum = 0.f;
#pragma unroll 8
            for (int s = 0; s < S_; s++) { float t = xs[tid + s]; sum += t * t; }
            g_invh[bc * W_ + w] = __float2half(1.f / fmaxf(sqrtf(sum), EPS_));
        }
    } else {
        __shared__ float wsum[8];
        int idx = blockIdx.x - 1024;              // 0..511
        int p = idx * 2 + (tid >> 7);             // (c,k) pair id, 0..1023
        int c = p >> 8, k = p & 255;
        int s = tid & 127;
        float v = shp[(c * K_ + k) * S_ + s];
        float sq = v * v;
#pragma unroll
        for (int o = 16; o > 0; o >>= 1) sq += __shfl_xor_sync(0xffffffffu, sq, o);
        if ((tid & 31) == 0) wsum[tid >> 5] = sq;
        __syncthreads();
        int g4 = (tid >> 7) * 4;
        float tot = wsum[g4] + wsum[g4 + 1] + wsum[g4 + 2] + wsum[g4 + 3];
        float inv = 1.f / fmaxf(sqrtf(tot), EPS_);
        int tile = (k >> 7) * C_ + c;
        int row = k & 127;
        uint32_t off = (uint32_t)row * 256u
                     + ((((uint32_t)(s >> 3)) ^ (row & 7)) << 4)
                     + (uint32_t)(s & 7) * 2u;
        *(half*)((char*)g_shpB + (size_t)tile * 32768 + off) = __float2half(v * inv);
    }
}

// ---------------------------------------------------------------------------
__device__ __forceinline__ void ldsm4(uint32_t (&r)[4], uint32_t addr) {
    asm volatile("ldmatrix.sync.aligned.m8n8.x4.shared.b16 {%0,%1,%2,%3}, [%4];"
                 : "=r"(r[0]), "=r"(r[1]), "=r"(r[2]), "=r"(r[3]) : "r"(addr));
}
__device__ __forceinline__ void mma16816(float (&d)[4], const uint32_t (&a)[4],
                                         uint32_t b0, uint32_t b1) {
    asm volatile("mma.sync.aligned.m16n8k16.row.col.f32.f16.f16.f32 "
                 "{%0,%1,%2,%3}, {%4,%5,%6,%7}, {%8,%9}, {%0,%1,%2,%3};"
                 : "+f"(d[0]), "+f"(d[1]), "+f"(d[2]), "+f"(d[3])
                 : "r"(a[0]), "r"(a[1]), "r"(a[2]), "r"(a[3]), "r"(b0), "r"(b1));
}
__device__ __forceinline__ void cp16(uint32_t dst, const void* src) {
    asm volatile("cp.async.cg.shared.global [%0], [%1], 16;"
                 :: "r"(dst), "l"(src) : "memory");
}
__device__ __forceinline__ uint32_t hm2(uint32_t v, half2 s) {
    half2 r = __hmul2(*(half2*)&v, s);
    return *(uint32_t*)&r;
}

// dynamic smem layout (bytes)
#define SM_B     0                 // 3 x 32768 : B tiles (triple buffer)
#define SM_STRIP 98304             // 3 x 2048 : per-channel strips
//   per buffer: even half2 @ +0 (512B), odd half2 @ +576 (512B), ivh @ +1088 (256B)
#define SM_MAX   104448            // 512 : per-k running max
#define SMEM_TOT 104960

// ---------------------------------------------------------------------------
// Main: 256 thr = 8 warps as 2(w) x 4(k); warp tile 64w x 32k; fp16 MMA,
// f32 accumulate across channels. A-fragments loaded DIRECTLY from the dual
// even/odd half2 strips (no A smem tile), iv folded in registers via hmul2.
// Triple-buffered B + strips -> 1 sync per channel. 2 CTAs/SM.
// ---------------------------------------------------------------------------
__global__ void __launch_bounds__(256, 2) k_main(const float* __restrict__ x,
                                                 float* __restrict__ out) {
    extern __shared__ char dsm[];
    float* smax = (float*)(dsm + SM_MAX);
    const uint32_t sB0 = (uint32_t)__cvta_generic_to_shared(dsm + SM_B);

    const int tid  = threadIdx.x;
    const int lane = tid & 31, wid = tid >> 5;
    const int ww = wid & 1;            // w direction (64 rows each)
    const int wk = wid >> 1;           // k direction (32 cols each)
    const int w0 = blockIdx.x * WT, k0 = blockIdx.y * KT, b = blockIdx.z;

    if (tid < KT) smax[tid] = 0.f;

    // A-fragment strip addressing (per lane)
    const int par = (lane >> 2) & 1;                     // row parity -> e/o strip
    const int qb  = ((ww * 64 + (lane >> 2)) >> 1) + (lane & 3);
    // B ldmatrix lane addressing
    const int brow = wk * 32 + ((lane >> 4) & 1) * 8 + (lane & 7);   // + p*16
    const int bhi  = (lane >> 3) & 1;

    float acc[4][4][4];
#pragma unroll
    for (int mi = 0; mi < 4; mi++)
#pragma unroll
        for (int ni = 0; ni < 4; ni++)
#pragma unroll
            for (int d = 0; d < 4; d++) acc[mi][ni][d] = 0.f;

    // ---- strip staging: threads 0..127 dual half2 strips, 128..255 ivh ------
#define STAGE_STRIP(ch, bf) do {                                               \
        char* sp = dsm + SM_STRIP + (bf) * 2048;                               \
        if (tid < 128) {                                                       \
            const float* xg = x + ((b * C_ + (ch)) * L_) + w0;                 \
            int i0 = 2 * tid;                                                  \
            float f0 = (w0 + i0     < L_) ? xg[i0]     : 0.f;                  \
            float f1 = (w0 + i0 + 1 < L_) ? xg[i0 + 1] : 0.f;                  \
            float f2 = (w0 + i0 + 2 < L_) ? xg[i0 + 2] : 0.f;                  \
            half2 e = __floats2half2_rn(f0, f1);                               \
            half2 o = __floats2half2_rn(f1, f2);                               \
            ((uint32_t*)(sp))[tid]        = *(uint32_t*)&e;                    \
            ((uint32_t*)(sp + 576))[tid]  = *(uint32_t*)&o;                    \
        } else {                                                               \
            int w = w0 + tid - 128;                                            \
            ((half*)(sp + 1088))[tid - 128] =                                  \
                (w < W_) ? g_invh[(b * C_ + (ch)) * W_ + w] : __float2half(0.f);\
        }                                                                      \
    } while (0)

#define STAGE_B(ch, bf) do {                                                   \
        const char* src = (const char*)g_shpB                                  \
                        + (size_t)(blockIdx.y * C_ + (ch)) * 32768;            \
        uint32_t dst = sB0 + (bf) * 32768;                                     \
        _Pragma("unroll")                                                      \
        for (int j = 0; j < 8; j++) {                                          \
            int idx = tid + 256 * j;                                           \
            cp16(dst + idx * 16, src + idx * 16);                              \
        }                                                                      \
        asm volatile("cp.async.commit_group;" ::: "memory");                   \
    } while (0)

    STAGE_STRIP(0, 0);
    STAGE_B(0, 0);

    for (int c = 0; c < C_; c++) {
        const int cb = c % 3;
        if (c + 1 < C_) {
            STAGE_STRIP(c + 1, (c + 1) % 3);
            STAGE_B(c + 1, (c + 1) % 3);
            asm volatile("cp.async.wait_group 1;" ::: "memory");
        } else {
            asm volatile("cp.async.wait_group 0;" ::: "memory");
        }
        __syncthreads();   // B_c landed, strip_c visible; buffers c+1 in flight

        char* sp = dsm + SM_STRIP + cb * 2048;
        const uint32_t* sv = (const uint32_t*)(sp + (par ? 576 : 0));
        const half* ivh = (const half*)(sp + 1088);

        // per-mi iv broadcasts + rolling strip window init
        half2 ivlo[4], ivhi[4];
        uint32_t vA[4];
#pragma unroll
        for (int mi = 0; mi < 4; mi++) {
            int r0 = ww * 64 + mi * 16 + (lane >> 2);
            ivlo[mi] = __half2half2(ivh[r0]);
            ivhi[mi] = __half2half2(ivh[r0 + 8]);
            vA[mi] = sv[qb + mi * 8];
        }

        const uint32_t sB = sB0 + cb * 32768;
#pragma unroll
        for (int st = 0; st < 8; st++) {
            // A fragments straight from strips: 2 new LDS.32 per mi per step
            uint32_t a[4][4];
#pragma unroll
            for (int mi = 0; mi < 4; mi++) {
                uint32_t vB = sv[qb + mi * 8 + 8 * st + 4];
                uint32_t vC = sv[qb + mi * 8 + 8 * st + 8];
                a[mi][0] = hm2(vA[mi], ivlo[mi]);
                a[mi][1] = hm2(vB,     ivhi[mi]);
                a[mi][2] = hm2(vB,     ivlo[mi]);
                a[mi][3] = hm2(vC,     ivhi[mi]);
                vA[mi] = vC;
            }
            // B fragments: 2 ldmatrix.x4 cover 32 k-rows x 16 s
            uint32_t bb[2][4];
#pragma unroll
            for (int p = 0; p < 2; p++) {
                int row = brow + p * 16;
                uint32_t ad = sB + row * 256 + (((2 * st + bhi) ^ (row & 7)) << 4);
                ldsm4(bb[p], ad);
            }
#pragma unroll
            for (int mi = 0; mi < 4; mi++)
#pragma unroll
                for (int p = 0; p < 2; p++) {
                    mma16816(acc[mi][2 * p + 0], a[mi], bb[p][0], bb[p][1]);
                    mma16816(acc[mi][2 * p + 1], a[mi], bb[p][2], bb[p][3]);
                }
        }
        // no trailing sync: writers at iter c+1 target buffer (c+2)%3,
        // readers here use (c)%3 -- disjoint; one sync per channel suffices.
    }

    // ---- epilogue: relu + max over w, reduce to out[b][k] -------------------
#pragma unroll
    for (int ni = 0; ni < 4; ni++) {
#pragma unroll
        for (int cc = 0; cc < 2; cc++) {
            float m = 0.f;
#pragma unroll
            for (int mi = 0; mi < 4; mi++)
                m = fmaxf(m, fmaxf(acc[mi][ni][cc], acc[mi][ni][cc + 2]));
            m = fmaxf(m * 0.25f, 0.f);
            m = fmaxf(m, __shfl_xor_sync(0xffffffffu, m, 4));
            m = fmaxf(m, __shfl_xor_sync(0xffffffffu, m, 8));
            m = fmaxf(m, __shfl_xor_sync(0xffffffffu, m, 16));
            if (lane < 4)
                atomicMax((int*)&smax[wk * 32 + ni * 8 + 2 * lane + cc],
                          __float_as_int(m));
        }
    }
    __syncthreads();
    if (tid < KT)
        atomicMax((int*)&out[b * K_ + k0 + tid], __float_as_int(smax[tid]));
}

// ---------------------------------------------------------------------------
extern "C" void kernel_launch(void* const* d_in, const int* in_sizes, int n_in,
                              void* d_out, int out_size) {
    const float* x   = (const float*)d_in[0];   // (16,4,4096)
    const float* shp = (const float*)d_in[1];   // (4,256,128)
    float* out = (float*)d_out;                 // (16,1,256)

    static int attr_done = 0;
    if (!attr_done) {
        cudaFuncSetAttribute(k_main, cudaFuncAttributeMaxDynamicSharedMemorySize,
                             SMEM_TOT);
        attr_done = 1;
    }

    k_prep<<<1536, 256>>>(x, shp, out);
    k_main<<<dim3((W_ + WT - 1) / WT, K_ / KT, B_), 256, SMEM_TOT>>>(x, out);
}